// round 7
// baseline (speedup 1.0000x reference)
#include <cuda_runtime.h>

#define E_EDGES 2000000
#define N_NODES 50000
#define D 32
#define NPAIRS (E_EDGES / 32)   // 62500 tile-pairs (32 edges each)

// ---------------- scratch ----------------
__device__ float    g_s0[N_NODES * D];          // segment sums layer 0 (fp32 accum)
__device__ float    g_s1[N_NODES * D];          // segment sums layer 1 (fp32 accum)
__device__ unsigned g_sh[N_NODES * 32];         // fp16 s-table: [node][32 half2]; 0-15 = s0, 16-31 = s1
__device__ float    g_dsum[N_NODES];            // softmax denominators

__device__ __forceinline__ float lrelu(float x) { return fmaxf(x, 0.01f * x); }
__device__ __forceinline__ void red_add2(float* p, float a, float b) {
    asm volatile("red.global.add.v2.f32 [%0], {%1,%2};" :: "l"(p), "f"(a), "f"(b) : "memory");
}
__device__ __forceinline__ void red_add1(float* p, float v) {
    asm volatile("red.global.add.f32 [%0], %1;" :: "l"(p), "f"(v) : "memory");
}

// pack two f32 -> f16x2 (lo = first element)
__device__ __forceinline__ unsigned packh2(float lo, float hi) {
    unsigned r; asm("cvt.rn.f16x2.f32 %0, %1, %2;" : "=r"(r) : "f"(hi), "f"(lo)); return r;
}

// m16n8k16 fp16 MMA, fp32 accum
__device__ __forceinline__ void mma16(float& c0, float& c1, float& c2, float& c3,
                                      unsigned a0, unsigned a1, unsigned a2, unsigned a3,
                                      unsigned b0, unsigned b1) {
    asm("mma.sync.aligned.m16n8k16.row.col.f32.f16.f16.f32 "
        "{%0,%1,%2,%3},{%4,%5,%6,%7},{%8,%9},{%0,%1,%2,%3};"
        : "+f"(c0), "+f"(c1), "+f"(c2), "+f"(c3)
        : "r"(a0), "r"(a1), "r"(a2), "r"(a3), "r"(b0), "r"(b1));
}

// dual-tile: C{1,2}[16,32] += A{1,2} @ W ; one B-frag LDS feeds both tiles
__device__ __forceinline__ void mm_tile2(const unsigned A1[2][4], const unsigned A2[2][4],
                                         const uint2* sB, float C1[4][4], float C2[4][4],
                                         int lane) {
#pragma unroll
    for (int kb = 0; kb < 2; kb++)
#pragma unroll
        for (int nb = 0; nb < 4; nb++) {
            uint2 b = sB[(kb * 4 + nb) * 32 + lane];
            mma16(C1[nb][0], C1[nb][1], C1[nb][2], C1[nb][3],
                  A1[kb][0], A1[kb][1], A1[kb][2], A1[kb][3], b.x, b.y);
            mma16(C2[nb][0], C2[nb][1], C2[nb][2], C2[nb][3],
                  A2[kb][0], A2[kb][1], A2[kb][2], A2[kb][3], b.x, b.y);
        }
}

// chain: C-frag -> A-frag of next matmul (adjacent-pair packing)
__device__ __forceinline__ void c2a(const float C[4][4], unsigned A[2][4]) {
#pragma unroll
    for (int kb = 0; kb < 2; kb++) {
        A[kb][0] = packh2(C[2 * kb][0],     C[2 * kb][1]);
        A[kb][1] = packh2(C[2 * kb][2],     C[2 * kb][3]);
        A[kb][2] = packh2(C[2 * kb + 1][0], C[2 * kb + 1][1]);
        A[kb][3] = packh2(C[2 * kb + 1][2], C[2 * kb + 1][3]);
    }
}

__device__ __forceinline__ void lrelu16(float C[4][4]) {
#pragma unroll
    for (int b = 0; b < 4; b++)
#pragma unroll
        for (int r = 0; r < 4; r++) C[b][r] = lrelu(C[b][r]);
}

// fp16 gather: A-frag regs load directly as half2 units from g_sh rows
__device__ __forceinline__ void gather_h(const unsigned* __restrict__ b0,
                                         const unsigned* __restrict__ b1,
                                         unsigned A[2][4], int t) {
#pragma unroll
    for (int kb = 0; kb < 2; kb++) {
        A[kb][0] = b0[8 * kb + t];
        A[kb][1] = b1[8 * kb + t];
        A[kb][2] = b0[8 * kb + t + 4];
        A[kb][3] = b1[8 * kb + t + 4];
    }
}

// bias-init both tiles' accumulators
__device__ __forceinline__ void binit2(float C1[4][4], float C2[4][4],
                                       const float* sB, int t) {
#pragma unroll
    for (int nb = 0; nb < 4; nb++) {
        float2 B2 = *(const float2*)&sB[8 * nb + 2 * t];
        C1[nb][0] = B2.x; C1[nb][1] = B2.y; C1[nb][2] = B2.x; C1[nb][3] = B2.y;
        C2[nb][0] = B2.x; C2[nb][1] = B2.y; C2[nb][2] = B2.x; C2[nb][3] = B2.y;
    }
}

// rank-1-fold init: C = a*P + Q per row
__device__ __forceinline__ void pqinit2(float C1[4][4], float C2[4][4],
                                        const float* sP, const float* sQ,
                                        float aA1, float aB1, float aA2, float aB2, int t) {
#pragma unroll
    for (int nb = 0; nb < 4; nb++) {
        float2 P = *(const float2*)&sP[8 * nb + 2 * t];
        float2 Q = *(const float2*)&sQ[8 * nb + 2 * t];
        C1[nb][0] = fmaf(aA1, P.x, Q.x); C1[nb][1] = fmaf(aA1, P.y, Q.y);
        C1[nb][2] = fmaf(aB1, P.x, Q.x); C1[nb][3] = fmaf(aB1, P.y, Q.y);
        C2[nb][0] = fmaf(aA2, P.x, Q.x); C2[nb][1] = fmaf(aA2, P.y, Q.y);
        C2[nb][2] = fmaf(aB2, P.x, Q.x); C2[nb][3] = fmaf(aB2, P.y, Q.y);
    }
}

// scatter one tile's C into a node table
__device__ __forceinline__ void scat(float* pA, float* pB, const float C[4][4], int t) {
#pragma unroll
    for (int nb = 0; nb < 4; nb++) {
        int u0 = 8 * nb + 2 * t;
        red_add2(pA + u0, C[nb][0], C[nb][1]);
        red_add2(pB + u0, C[nb][2], C[nb][3]);
    }
}

// fill fp16 B-fragments (weight prep, once per block)
__device__ void fill_bfrag(uint2* dst, const float* __restrict__ W, int kblocks) {
    for (int i = threadIdx.x; i < kblocks * 4 * 32; i += blockDim.x) {
        int lane = i & 31, pi = i >> 5;
        int kb = pi >> 2, nb = pi & 3;
        int t = lane & 3, g = lane >> 2;
        int col = 8 * nb + g;
        int k0r = 16 * kb + 2 * t;
        uint2 v;
        v.x = packh2(W[k0r * 32 + col],       W[(k0r + 1) * 32 + col]);
        v.y = packh2(W[(k0r + 8) * 32 + col], W[(k0r + 9) * 32 + col]);
        dst[pi * 32 + lane] = v;
    }
}

// ---------------- init / convert ----------------
__global__ void kinit() {
    int i = blockIdx.x * blockDim.x + threadIdx.x;
    if (i < N_NODES * D) { g_s0[i] = 0.f; g_s1[i] = 0.f; }
    if (i < N_NODES)     { g_dsum[i] = 0.f; }
}
__global__ void kcvt0() {
    int i = blockIdx.x * blockDim.x + threadIdx.x;
    if (i >= N_NODES * 16) return;
    int n = i >> 4, c = i & 15;
    g_sh[n * 32 + c] = packh2(g_s0[n * 32 + 2 * c], g_s0[n * 32 + 2 * c + 1]);
}
__global__ void kcvt1() {
    int i = blockIdx.x * blockDim.x + threadIdx.x;
    if (i >= N_NODES * 16) return;
    int n = i >> 4, c = i & 15;
    g_sh[n * 32 + 16 + c] = packh2(g_s1[n * 32 + 2 * c], g_s1[n * 32 + 2 * c + 1]);
}

// ---------------- K0: t0 = TMLP0(h0) (rank-1 folded) -> scatter s0 ----------------
__global__ __launch_bounds__(256, 2)
void k0(const float* __restrict__ ea, const int* __restrict__ idx,
        const float* __restrict__ w_in, const float* __restrict__ b_in,
        const float* __restrict__ tw1, const float* __restrict__ tb1,
        const float* __restrict__ tw2, const float* __restrict__ tb2) {
    __shared__ uint2 sT2[256];
    __shared__ __align__(8) float sPT[32], sQT[32], sTB2[32];
    int tid = threadIdx.x;
    if (tid < 32) {
        float p = 0.f, qv = 0.f;
        for (int k = 0; k < 32; ++k) {
            p  = fmaf(w_in[k], tw1[k * 32 + tid], p);
            qv = fmaf(b_in[k], tw1[k * 32 + tid], qv);
        }
        sPT[tid] = p; sQT[tid] = qv + tb1[tid];
        sTB2[tid] = tb2[tid];
    }
    fill_bfrag(sT2, tw2, 2);
    __syncthreads();

    int lane = tid & 31, warp = tid >> 5;
    int t = lane & 3, g = lane >> 2;
    for (int tp = blockIdx.x * 8 + warp; tp < NPAIRS; tp += gridDim.x * 8) {
        int e0 = tp * 32;
        int eA1 = e0 + g, eB1 = eA1 + 8, eA2 = eA1 + 16, eB2 = eA1 + 24;
        float aA1 = ea[eA1], aB1 = ea[eB1], aA2 = ea[eA2], aB2 = ea[eB2];
        int nA1 = idx[eA1], nB1 = idx[eB1], nA2 = idx[eA2], nB2 = idx[eB2];

        unsigned A1[2][4], A2[2][4];
#pragma unroll
        for (int kb = 0; kb < 2; kb++) {
            int c0 = 16 * kb + 2 * t;
            float2 P0 = *(const float2*)&sPT[c0],     Q0 = *(const float2*)&sQT[c0];
            float2 P1 = *(const float2*)&sPT[c0 + 8], Q1 = *(const float2*)&sQT[c0 + 8];
            A1[kb][0] = packh2(lrelu(fmaf(aA1, P0.x, Q0.x)), lrelu(fmaf(aA1, P0.y, Q0.y)));
            A1[kb][1] = packh2(lrelu(fmaf(aB1, P0.x, Q0.x)), lrelu(fmaf(aB1, P0.y, Q0.y)));
            A1[kb][2] = packh2(lrelu(fmaf(aA1, P1.x, Q1.x)), lrelu(fmaf(aA1, P1.y, Q1.y)));
            A1[kb][3] = packh2(lrelu(fmaf(aB1, P1.x, Q1.x)), lrelu(fmaf(aB1, P1.y, Q1.y)));
            A2[kb][0] = packh2(lrelu(fmaf(aA2, P0.x, Q0.x)), lrelu(fmaf(aA2, P0.y, Q0.y)));
            A2[kb][1] = packh2(lrelu(fmaf(aB2, P0.x, Q0.x)), lrelu(fmaf(aB2, P0.y, Q0.y)));
            A2[kb][2] = packh2(lrelu(fmaf(aA2, P1.x, Q1.x)), lrelu(fmaf(aA2, P1.y, Q1.y)));
            A2[kb][3] = packh2(lrelu(fmaf(aB2, P1.x, Q1.x)), lrelu(fmaf(aB2, P1.y, Q1.y)));
        }
        float C1[4][4], C2[4][4];
        binit2(C1, C2, sTB2, t);
        mm_tile2(A1, A2, sT2, C1, C2, lane);

        scat(g_s0 + (size_t)nA1 * 32, g_s0 + (size_t)nB1 * 32, C1, t);
        scat(g_s0 + (size_t)nA2 * 32, g_s0 + (size_t)nB2 * 32, C2, t);
    }
}

// ---------------- K1: h1 = UPD0(h0,s0[idx]); t1 = TMLP1(h1) -> scatter s1 ---------
__global__ __launch_bounds__(256, 2)
void k1(const float* __restrict__ ea, const int* __restrict__ idx,
        const float* __restrict__ w_in, const float* __restrict__ b_in,
        const float* __restrict__ tw1, const float* __restrict__ tb1,
        const float* __restrict__ tw2, const float* __restrict__ tb2,
        const float* __restrict__ uw1, const float* __restrict__ ub1,
        const float* __restrict__ uw2, const float* __restrict__ ub2) {
    __shared__ uint2 sU1b[256], sU2[256], sT1[256], sT2[256];
    __shared__ __align__(8) float sPU[32], sQU[32], sUB2[32], sTB1[32], sTB2[32];
    int tid = threadIdx.x;
    if (tid < 32) {
        float p = 0.f, qv = 0.f;
        for (int k = 0; k < 32; ++k) {
            p  = fmaf(w_in[k], uw1[k * 32 + tid], p);
            qv = fmaf(b_in[k], uw1[k * 32 + tid], qv);
        }
        sPU[tid] = p; sQU[tid] = qv + ub1[tid];
        sUB2[tid] = ub2[tid];
        sTB1[tid] = tb1[32 + tid];
        sTB2[tid] = tb2[32 + tid];
    }
    fill_bfrag(sU1b, uw1 + 1024, 2);
    fill_bfrag(sU2,  uw2, 2);
    fill_bfrag(sT1,  tw1 + 1024, 2);
    fill_bfrag(sT2,  tw2 + 1024, 2);
    __syncthreads();

    int lane = tid & 31, warp = tid >> 5;
    int t = lane & 3, g = lane >> 2;
    for (int tp = blockIdx.x * 8 + warp; tp < NPAIRS; tp += gridDim.x * 8) {
        int e0 = tp * 32;
        int eA1 = e0 + g, eB1 = eA1 + 8, eA2 = eA1 + 16, eB2 = eA1 + 24;
        float aA1 = ea[eA1], aB1 = ea[eB1], aA2 = ea[eA2], aB2 = ea[eB2];
        int nA1 = idx[eA1], nB1 = idx[eB1], nA2 = idx[eA2], nB2 = idx[eB2];

        unsigned A1[2][4], A2[2][4];
        gather_h(g_sh + (size_t)nA1 * 32, g_sh + (size_t)nB1 * 32, A1, t);
        gather_h(g_sh + (size_t)nA2 * 32, g_sh + (size_t)nB2 * 32, A2, t);

        float C1[4][4], C2[4][4];
        pqinit2(C1, C2, sPU, sQU, aA1, aB1, aA2, aB2, t);
        mm_tile2(A1, A2, sU1b, C1, C2, lane);
        lrelu16(C1); lrelu16(C2);
        c2a(C1, A1); c2a(C2, A2);

        float H1[4][4], H2[4][4];
        binit2(H1, H2, sUB2, t);
        mm_tile2(A1, A2, sU2, H1, H2, lane);        // H = h1

        // T layer 1
        c2a(H1, A1); c2a(H2, A2);
        binit2(C1, C2, sTB1, t);
        mm_tile2(A1, A2, sT1, C1, C2, lane);
        lrelu16(C1); lrelu16(C2);
        c2a(C1, A1); c2a(C2, A2);
        binit2(C1, C2, sTB2, t);
        mm_tile2(A1, A2, sT2, C1, C2, lane);

        scat(g_s1 + (size_t)nA1 * 32, g_s1 + (size_t)nB1 * 32, C1, t);
        scat(g_s1 + (size_t)nA2 * 32, g_s1 + (size_t)nB2 * 32, C2, t);
    }
}

// ---- K2: recompute h1 from s0h; h2 = UPD1; head; exp; red denom -------------------
__global__ __launch_bounds__(256, 2)
void k2(const float* __restrict__ ea, const int* __restrict__ idx,
        const float* __restrict__ w_in, const float* __restrict__ b_in,
        const float* __restrict__ uw1, const float* __restrict__ ub1,
        const float* __restrict__ uw2, const float* __restrict__ ub2,
        const float* __restrict__ hw1, const float* __restrict__ hb1,
        const float* __restrict__ hw2, const float* __restrict__ hb2,
        const float* __restrict__ hw3, const float* __restrict__ hb3,
        float* __restrict__ out) {
    __shared__ uint2 sU1[512];                  // uw1[1] full 64x32 (4 kblocks)
    __shared__ uint2 sU2[256], sH1b[256], sH2[256];
    __shared__ uint2 sU1b0[256], sU20[256];
    __shared__ __align__(8) float sUB1[32], sUB2[32], sPH[32], sQH[32], sHB2[32], sH3[32];
    __shared__ __align__(8) float sPU[32], sQU[32], sUB20[32];
    __shared__ float sHB3;
    int tid = threadIdx.x;
    const float* u1 = uw1 + 2048;
    if (tid < 32) {
        float p = 0.f, qv = 0.f, pu = 0.f, qu = 0.f;
        for (int k = 0; k < 32; ++k) {
            p  = fmaf(w_in[k], hw1[k * 32 + tid], p);
            qv = fmaf(b_in[k], hw1[k * 32 + tid], qv);
            pu = fmaf(w_in[k], uw1[k * 32 + tid], pu);
            qu = fmaf(b_in[k], uw1[k * 32 + tid], qu);
        }
        sPH[tid] = p;  sQH[tid] = qv + hb1[tid];
        sPU[tid] = pu; sQU[tid] = qu + ub1[tid];
        sUB20[tid] = ub2[tid];
        sUB1[tid] = ub1[32 + tid];
        sUB2[tid] = ub2[32 + tid];
        sHB2[tid] = hb2[tid];
        sH3[tid]  = hw3[tid];
    }
    if (tid == 0) sHB3 = hb3[0];
    fill_bfrag(sU1,   u1, 4);
    fill_bfrag(sU2,   uw2 + 1024, 2);
    fill_bfrag(sH1b,  hw1 + 1024, 2);
    fill_bfrag(sH2,   hw2, 2);
    fill_bfrag(sU1b0, uw1 + 1024, 2);
    fill_bfrag(sU20,  uw2, 2);
    __syncthreads();

    int lane = tid & 31, warp = tid >> 5;
    int t = lane & 3, g = lane >> 2;
    for (int tp = blockIdx.x * 8 + warp; tp < NPAIRS; tp += gridDim.x * 8) {
        int e0 = tp * 32;
        int eA1 = e0 + g, eB1 = eA1 + 8, eA2 = eA1 + 16, eB2 = eA1 + 24;
        float aA1 = ea[eA1], aB1 = ea[eB1], aA2 = ea[eA2], aB2 = ea[eB2];
        int nA1 = idx[eA1], nB1 = idx[eB1], nA2 = idx[eA2], nB2 = idx[eB2];
        const unsigned* bA1 = g_sh + (size_t)nA1 * 32;
        const unsigned* bB1 = g_sh + (size_t)nB1 * 32;
        const unsigned* bA2 = g_sh + (size_t)nA2 * 32;
        const unsigned* bB2 = g_sh + (size_t)nB2 * 32;

        // ---- recompute h1 from s0h ----
        unsigned A1[2][4], A2[2][4];
        gather_h(bA1, bB1, A1, t);
        gather_h(bA2, bB2, A2, t);
        float C1[4][4], C2[4][4];
        pqinit2(C1, C2, sPU, sQU, aA1, aB1, aA2, aB2, t);
        mm_tile2(A1, A2, sU1b0, C1, C2, lane);
        lrelu16(C1); lrelu16(C2);
        c2a(C1, A1); c2a(C2, A2);
        float H1[4][4], H2[4][4];
        binit2(H1, H2, sUB20, t);
        mm_tile2(A1, A2, sU20, H1, H2, lane);       // H = h1

        // ---- layer-1 update ----
        c2a(H1, A1); c2a(H2, A2);
        binit2(C1, C2, sUB1, t);
        mm_tile2(A1, A2, sU1, C1, C2, lane);
        gather_h(bA1 + 16, bB1 + 16, A1, t);        // s1 half of same row (L1 hit)
        gather_h(bA2 + 16, bB2 + 16, A2, t);
        mm_tile2(A1, A2, sU1 + 8 * 32, C1, C2, lane);
        lrelu16(C1); lrelu16(C2);

        c2a(C1, A1); c2a(C2, A2);
        binit2(H1, H2, sUB2, t);
        mm_tile2(A1, A2, sU2, H1, H2, lane);        // H = h2

        // ---- head ----
        c2a(H1, A1); c2a(H2, A2);
        pqinit2(C1, C2, sPH, sQH, aA1, aB1, aA2, aB2, t);
        mm_tile2(A1, A2, sH1b, C1, C2, lane);
        lrelu16(C1); lrelu16(C2);
        c2a(C1, A1); c2a(C2, A2);
        binit2(C1, C2, sHB2, t);
        mm_tile2(A1, A2, sH2, C1, C2, lane);
        lrelu16(C1); lrelu16(C2);

        // head dot + row reduce, both tiles
        float dA1 = 0.f, dB1 = 0.f, dA2 = 0.f, dB2 = 0.f;
#pragma unroll
        for (int nb = 0; nb < 4; nb++) {
            float2 h3 = *(const float2*)&sH3[8 * nb + 2 * t];
            dA1 = fmaf(C1[nb][0], h3.x, dA1); dA1 = fmaf(C1[nb][1], h3.y, dA1);
            dB1 = fmaf(C1[nb][2], h3.x, dB1); dB1 = fmaf(C1[nb][3], h3.y, dB1);
            dA2 = fmaf(C2[nb][0], h3.x, dA2); dA2 = fmaf(C2[nb][1], h3.y, dA2);
            dB2 = fmaf(C2[nb][2], h3.x, dB2); dB2 = fmaf(C2[nb][3], h3.y, dB2);
        }
        dA1 += __shfl_xor_sync(0xffffffffu, dA1, 1);
        dA1 += __shfl_xor_sync(0xffffffffu, dA1, 2);
        dB1 += __shfl_xor_sync(0xffffffffu, dB1, 1);
        dB1 += __shfl_xor_sync(0xffffffffu, dB1, 2);
        dA2 += __shfl_xor_sync(0xffffffffu, dA2, 1);
        dA2 += __shfl_xor_sync(0xffffffffu, dA2, 2);
        dB2 += __shfl_xor_sync(0xffffffffu, dB2, 1);
        dB2 += __shfl_xor_sync(0xffffffffu, dB2, 2);

        if (t == 0) {
            float exA1 = __expf(dA1 + sHB3), exB1 = __expf(dB1 + sHB3);
            float exA2 = __expf(dA2 + sHB3), exB2 = __expf(dB2 + sHB3);
            out[eA1] = exA1; out[eB1] = exB1;
            out[eA2] = exA2; out[eB2] = exB2;
            red_add1(&g_dsum[nA1], exA1);
            red_add1(&g_dsum[nB1], exB1);
            red_add1(&g_dsum[nA2], exA2);
            red_add1(&g_dsum[nB2], exB2);
        }
    }
}

// ---------------- K4: normalize ----------------
__global__ void k4(const int* __restrict__ idx, float* __restrict__ out) {
    int e = blockIdx.x * blockDim.x + threadIdx.x;
    if (e >= E_EDGES) return;
    out[e] = out[e] / g_dsum[idx[e]];
}

// ---------------- launcher ----------------
extern "C" void kernel_launch(void* const* d_in, const int* in_sizes, int n_in,
                              void* d_out, int out_size) {
    const float* ea   = (const float*)d_in[0];
    const int*   eidx = (const int*)d_in[1];
    const float* w_in = (const float*)d_in[2];
    const float* b_in = (const float*)d_in[3];
    const float* tw1  = (const float*)d_in[4];
    const float* tb1  = (const float*)d_in[5];
    const float* tw2  = (const float*)d_in[6];
    const float* tb2  = (const float*)d_in[7];
    const float* uw1  = (const float*)d_in[8];
    const float* ub1  = (const float*)d_in[9];
    const float* uw2  = (const float*)d_in[10];
    const float* ub2  = (const float*)d_in[11];
    const float* hw1  = (const float*)d_in[12];
    const float* hb1  = (const float*)d_in[13];
    const float* hw2  = (const float*)d_in[14];
    const float* hb2  = (const float*)d_in[15];
    const float* hw3  = (const float*)d_in[16];
    const float* hb3  = (const float*)d_in[17];
    float* out = (float*)d_out;

    const int TB = 256;
    kinit<<<(N_NODES * D + TB - 1) / TB, TB>>>();
    const int GB = 2048;
    int gcv = (N_NODES * 16 + TB - 1) / TB;
    k0<<<GB, 256>>>(ea, eidx, w_in, b_in, tw1, tb1, tw2, tb2);
    kcvt0<<<gcv, TB>>>();
    k1<<<GB, 256>>>(ea, eidx, w_in, b_in, tw1, tb1, tw2, tb2, uw1, ub1, uw2, ub2);
    kcvt1<<<gcv, TB>>>();
    k2<<<GB, 256>>>(ea, eidx, w_in, b_in, uw1, ub1, uw2, ub2,
                    hw1, hb1, hw2, hb2, hw3, hb3, out);
    int gb = (E_EDGES + TB - 1) / TB;
    k4<<<gb, TB>>>(eidx, out);
}

// round 8
// speedup vs baseline: 1.3231x; 1.3231x over previous
#include <cuda_runtime.h>

#define E_EDGES 2000000
#define N_NODES 50000
#define D 32
#define NTILES (E_EDGES / 16)

// ---------------- scratch ----------------
__device__ float    g_s0[N_NODES * D];      // segment sums layer 0 (fp32 accum)
__device__ float    g_s1[N_NODES * D];      // segment sums layer 1 (fp32 accum)
__device__ unsigned g_sh[N_NODES * 32];     // fp16 table: [node][32 half2]; 0-15 = s0, 16-31 = s1
__device__ float    g_dsum[N_NODES];        // softmax denominators

__device__ __forceinline__ float lrelu(float x) { return fmaxf(x, 0.01f * x); }
__device__ __forceinline__ void red_add2(float* p, float a, float b) {
    asm volatile("red.global.add.v2.f32 [%0], {%1,%2};" :: "l"(p), "f"(a), "f"(b) : "memory");
}
__device__ __forceinline__ void red_add1(float* p, float v) {
    asm volatile("red.global.add.f32 [%0], %1;" :: "l"(p), "f"(v) : "memory");
}

// pack two f32 -> f16x2 (lo = first element)
__device__ __forceinline__ unsigned packh2(float lo, float hi) {
    unsigned r; asm("cvt.rn.f16x2.f32 %0, %1, %2;" : "=r"(r) : "f"(hi), "f"(lo)); return r;
}

// m16n8k16 fp16 MMA, fp32 accum
__device__ __forceinline__ void mma16(float& c0, float& c1, float& c2, float& c3,
                                      unsigned a0, unsigned a1, unsigned a2, unsigned a3,
                                      unsigned b0, unsigned b1) {
    asm("mma.sync.aligned.m16n8k16.row.col.f32.f16.f16.f32 "
        "{%0,%1,%2,%3},{%4,%5,%6,%7},{%8,%9},{%0,%1,%2,%3};"
        : "+f"(c0), "+f"(c1), "+f"(c2), "+f"(c3)
        : "r"(a0), "r"(a1), "r"(a2), "r"(a3), "r"(b0), "r"(b1));
}

// C[16,32] += A[16,32] @ W   (2 kblocks x 4 nblocks, fp16)
__device__ __forceinline__ void mm_tile(const unsigned A[2][4], const uint2* sB,
                                        float C[4][4], int lane) {
#pragma unroll
    for (int kb = 0; kb < 2; kb++)
#pragma unroll
        for (int nb = 0; nb < 4; nb++) {
            uint2 b = sB[(kb * 4 + nb) * 32 + lane];
            mma16(C[nb][0], C[nb][1], C[nb][2], C[nb][3],
                  A[kb][0], A[kb][1], A[kb][2], A[kb][3], b.x, b.y);
        }
}

// chain: C-frag -> A-frag of next matmul (adjacent-pair packing)
__device__ __forceinline__ void c2a(const float C[4][4], unsigned A[2][4]) {
#pragma unroll
    for (int kb = 0; kb < 2; kb++) {
        A[kb][0] = packh2(C[2 * kb][0],     C[2 * kb][1]);
        A[kb][1] = packh2(C[2 * kb][2],     C[2 * kb][3]);
        A[kb][2] = packh2(C[2 * kb + 1][0], C[2 * kb + 1][1]);
        A[kb][3] = packh2(C[2 * kb + 1][2], C[2 * kb + 1][3]);
    }
}

__device__ __forceinline__ void lrelu16(float C[4][4]) {
#pragma unroll
    for (int b = 0; b < 4; b++)
#pragma unroll
        for (int r = 0; r < 4; r++) C[b][r] = lrelu(C[b][r]);
}

// fp16 gather: A-frag regs load directly as half2 words from g_sh rows
__device__ __forceinline__ void gather_h(const unsigned* __restrict__ b0,
                                         const unsigned* __restrict__ b1,
                                         unsigned A[2][4], int t) {
#pragma unroll
    for (int kb = 0; kb < 2; kb++) {
        A[kb][0] = b0[8 * kb + t];
        A[kb][1] = b1[8 * kb + t];
        A[kb][2] = b0[8 * kb + t + 4];
        A[kb][3] = b1[8 * kb + t + 4];
    }
}

// bias-init accumulators
__device__ __forceinline__ void binit(float C[4][4], const float* sB, int t) {
#pragma unroll
    for (int nb = 0; nb < 4; nb++) {
        float2 B2 = *(const float2*)&sB[8 * nb + 2 * t];
        C[nb][0] = B2.x; C[nb][1] = B2.y; C[nb][2] = B2.x; C[nb][3] = B2.y;
    }
}

// rank-1-fold init: C = a*P + Q per row
__device__ __forceinline__ void pqinit(float C[4][4], const float* sP, const float* sQ,
                                       float aA, float aB, int t) {
#pragma unroll
    for (int nb = 0; nb < 4; nb++) {
        float2 P = *(const float2*)&sP[8 * nb + 2 * t];
        float2 Q = *(const float2*)&sQ[8 * nb + 2 * t];
        C[nb][0] = fmaf(aA, P.x, Q.x); C[nb][1] = fmaf(aA, P.y, Q.y);
        C[nb][2] = fmaf(aB, P.x, Q.x); C[nb][3] = fmaf(aB, P.y, Q.y);
    }
}

// scatter C into node tables
__device__ __forceinline__ void scat(float* pA, float* pB, const float C[4][4], int t) {
#pragma unroll
    for (int nb = 0; nb < 4; nb++) {
        int u0 = 8 * nb + 2 * t;
        red_add2(pA + u0, C[nb][0], C[nb][1]);
        red_add2(pB + u0, C[nb][2], C[nb][3]);
    }
}

// fill fp16 B-fragments (weight prep, once per block)
__device__ void fill_bfrag(uint2* dst, const float* __restrict__ W, int kblocks) {
    for (int i = threadIdx.x; i < kblocks * 4 * 32; i += blockDim.x) {
        int lane = i & 31, pi = i >> 5;
        int kb = pi >> 2, nb = pi & 3;
        int t = lane & 3, g = lane >> 2;
        int col = 8 * nb + g;
        int k0r = 16 * kb + 2 * t;
        uint2 v;
        v.x = packh2(W[k0r * 32 + col],       W[(k0r + 1) * 32 + col]);
        v.y = packh2(W[(k0r + 8) * 32 + col], W[(k0r + 9) * 32 + col]);
        dst[pi * 32 + lane] = v;
    }
}

// ---------------- init / convert ----------------
__global__ void kinit() {
    int i = blockIdx.x * blockDim.x + threadIdx.x;
    if (i < N_NODES * D) { g_s0[i] = 0.f; g_s1[i] = 0.f; }
    if (i < N_NODES)     { g_dsum[i] = 0.f; }
}
__global__ void kcvt0() {
    int i = blockIdx.x * blockDim.x + threadIdx.x;
    if (i >= N_NODES * 16) return;
    int n = i >> 4, c = i & 15;
    g_sh[n * 32 + c] = packh2(g_s0[n * 32 + 2 * c], g_s0[n * 32 + 2 * c + 1]);
}
__global__ void kcvt1() {
    int i = blockIdx.x * blockDim.x + threadIdx.x;
    if (i >= N_NODES * 16) return;
    int n = i >> 4, c = i & 15;
    g_sh[n * 32 + 16 + c] = packh2(g_s1[n * 32 + 2 * c], g_s1[n * 32 + 2 * c + 1]);
}

// ---------------- K0: t0 = TMLP0(h0) (rank-1 folded) -> scatter s0 ----------------
__global__ __launch_bounds__(128, 5)
void k0(const float* __restrict__ ea, const int* __restrict__ idx,
        const float* __restrict__ w_in, const float* __restrict__ b_in,
        const float* __restrict__ tw1, const float* __restrict__ tb1,
        const float* __restrict__ tw2, const float* __restrict__ tb2) {
    __shared__ uint2 sT2[256];
    __shared__ __align__(8) float sPT[32], sQT[32], sTB2[32];
    int tid = threadIdx.x;
    if (tid < 32) {
        float p = 0.f, qv = 0.f;
        for (int k = 0; k < 32; ++k) {
            p  = fmaf(w_in[k], tw1[k * 32 + tid], p);
            qv = fmaf(b_in[k], tw1[k * 32 + tid], qv);
        }
        sPT[tid] = p; sQT[tid] = qv + tb1[tid];
        sTB2[tid] = tb2[tid];
    }
    fill_bfrag(sT2, tw2, 2);
    __syncthreads();

    int lane = tid & 31, warp = tid >> 5;
    int t = lane & 3, g = lane >> 2;
    for (int tile = blockIdx.x * 4 + warp; tile < NTILES; tile += gridDim.x * 4) {
        int e0 = tile * 16;
        int eA = e0 + g, eB = eA + 8;
        float aA = ea[eA], aB = ea[eB];
        int nA = idx[eA], nB = idx[eB];

        unsigned A[2][4];
#pragma unroll
        for (int kb = 0; kb < 2; kb++) {
            int c0 = 16 * kb + 2 * t;
            float2 P0 = *(const float2*)&sPT[c0],     Q0 = *(const float2*)&sQT[c0];
            float2 P1 = *(const float2*)&sPT[c0 + 8], Q1 = *(const float2*)&sQT[c0 + 8];
            A[kb][0] = packh2(lrelu(fmaf(aA, P0.x, Q0.x)), lrelu(fmaf(aA, P0.y, Q0.y)));
            A[kb][1] = packh2(lrelu(fmaf(aB, P0.x, Q0.x)), lrelu(fmaf(aB, P0.y, Q0.y)));
            A[kb][2] = packh2(lrelu(fmaf(aA, P1.x, Q1.x)), lrelu(fmaf(aA, P1.y, Q1.y)));
            A[kb][3] = packh2(lrelu(fmaf(aB, P1.x, Q1.x)), lrelu(fmaf(aB, P1.y, Q1.y)));
        }
        float C[4][4];
        binit(C, sTB2, t);
        mm_tile(A, sT2, C, lane);
        scat(g_s0 + (size_t)nA * 32, g_s0 + (size_t)nB * 32, C, t);
    }
}

// ---------------- K1: h1 = UPD0(h0,s0h[idx]); t1 = TMLP1(h1) -> scatter s1 --------
__global__ __launch_bounds__(128, 5)
void k1(const float* __restrict__ ea, const int* __restrict__ idx,
        const float* __restrict__ w_in, const float* __restrict__ b_in,
        const float* __restrict__ tw1, const float* __restrict__ tb1,
        const float* __restrict__ tw2, const float* __restrict__ tb2,
        const float* __restrict__ uw1, const float* __restrict__ ub1,
        const float* __restrict__ uw2, const float* __restrict__ ub2) {
    __shared__ uint2 sU1b[256], sU2[256], sT1[256], sT2[256];
    __shared__ __align__(8) float sPU[32], sQU[32], sUB2[32], sTB1[32], sTB2[32];
    int tid = threadIdx.x;
    if (tid < 32) {
        float p = 0.f, qv = 0.f;
        for (int k = 0; k < 32; ++k) {
            p  = fmaf(w_in[k], uw1[k * 32 + tid], p);
            qv = fmaf(b_in[k], uw1[k * 32 + tid], qv);
        }
        sPU[tid] = p; sQU[tid] = qv + ub1[tid];
        sUB2[tid] = ub2[tid];
        sTB1[tid] = tb1[32 + tid];
        sTB2[tid] = tb2[32 + tid];
    }
    fill_bfrag(sU1b, uw1 + 1024, 2);
    fill_bfrag(sU2,  uw2, 2);
    fill_bfrag(sT1,  tw1 + 1024, 2);
    fill_bfrag(sT2,  tw2 + 1024, 2);
    __syncthreads();

    int lane = tid & 31, warp = tid >> 5;
    int t = lane & 3, g = lane >> 2;
    for (int tile = blockIdx.x * 4 + warp; tile < NTILES; tile += gridDim.x * 4) {
        int e0 = tile * 16;
        int eA = e0 + g, eB = eA + 8;
        float aA = ea[eA], aB = ea[eB];
        int nA = idx[eA], nB = idx[eB];

        unsigned A[2][4];
        gather_h(g_sh + (size_t)nA * 32, g_sh + (size_t)nB * 32, A, t);

        float C[4][4];
        pqinit(C, sPU, sQU, aA, aB, t);
        mm_tile(A, sU1b, C, lane);
        lrelu16(C);
        c2a(C, A);

        float H[4][4];
        binit(H, sUB2, t);
        mm_tile(A, sU2, H, lane);       // H = h1

        // T layer 1
        c2a(H, A);
        binit(C, sTB1, t);
        mm_tile(A, sT1, C, lane);
        lrelu16(C);
        c2a(C, A);
        binit(C, sTB2, t);
        mm_tile(A, sT2, C, lane);

        scat(g_s1 + (size_t)nA * 32, g_s1 + (size_t)nB * 32, C, t);
    }
}

// ---- K2: recompute h1 from s0h; h2 = UPD1; head; exp; red denom -------------------
__global__ __launch_bounds__(128, 5)
void k2(const float* __restrict__ ea, const int* __restrict__ idx,
        const float* __restrict__ w_in, const float* __restrict__ b_in,
        const float* __restrict__ uw1, const float* __restrict__ ub1,
        const float* __restrict__ uw2, const float* __restrict__ ub2,
        const float* __restrict__ hw1, const float* __restrict__ hb1,
        const float* __restrict__ hw2, const float* __restrict__ hb2,
        const float* __restrict__ hw3, const float* __restrict__ hb3,
        float* __restrict__ out) {
    __shared__ uint2 sU1[512];                  // uw1[1] full 64x32 (4 kblocks)
    __shared__ uint2 sU2[256], sH1b[256], sH2[256];
    __shared__ uint2 sU1b0[256], sU20[256];
    __shared__ __align__(8) float sUB1[32], sUB2[32], sPH[32], sQH[32], sHB2[32], sH3[32];
    __shared__ __align__(8) float sPU[32], sQU[32], sUB20[32];
    __shared__ float sHB3;
    int tid = threadIdx.x;
    const float* u1 = uw1 + 2048;
    if (tid < 32) {
        float p = 0.f, qv = 0.f, pu = 0.f, qu = 0.f;
        for (int k = 0; k < 32; ++k) {
            p  = fmaf(w_in[k], hw1[k * 32 + tid], p);
            qv = fmaf(b_in[k], hw1[k * 32 + tid], qv);
            pu = fmaf(w_in[k], uw1[k * 32 + tid], pu);
            qu = fmaf(b_in[k], uw1[k * 32 + tid], qu);
        }
        sPH[tid] = p;  sQH[tid] = qv + hb1[tid];
        sPU[tid] = pu; sQU[tid] = qu + ub1[tid];
        sUB20[tid] = ub2[tid];
        sUB1[tid] = ub1[32 + tid];
        sUB2[tid] = ub2[32 + tid];
        sHB2[tid] = hb2[tid];
        sH3[tid]  = hw3[tid];
    }
    if (tid == 0) sHB3 = hb3[0];
    fill_bfrag(sU1,   u1, 4);
    fill_bfrag(sU2,   uw2 + 1024, 2);
    fill_bfrag(sH1b,  hw1 + 1024, 2);
    fill_bfrag(sH2,   hw2, 2);
    fill_bfrag(sU1b0, uw1 + 1024, 2);
    fill_bfrag(sU20,  uw2, 2);
    __syncthreads();

    int lane = tid & 31, warp = tid >> 5;
    int t = lane & 3, g = lane >> 2;
    for (int tile = blockIdx.x * 4 + warp; tile < NTILES; tile += gridDim.x * 4) {
        int e0 = tile * 16;
        int eA = e0 + g, eB = eA + 8;
        float aA = ea[eA], aB = ea[eB];
        int nA = idx[eA], nB = idx[eB];
        const unsigned* bA = g_sh + (size_t)nA * 32;
        const unsigned* bB = g_sh + (size_t)nB * 32;

        // ---- recompute h1 from s0h (words 0..15; same 128B line as s1) ----
        unsigned A[2][4];
        gather_h(bA, bB, A, t);
        float C[4][4];
        pqinit(C, sPU, sQU, aA, aB, t);
        mm_tile(A, sU1b0, C, lane);
        lrelu16(C);
        c2a(C, A);
        float H[4][4];
        binit(H, sUB20, t);
        mm_tile(A, sU20, H, lane);      // H = h1

        // ---- layer-1 update: C = UB1 + h1 @ U1[h] + s1 @ U1[s] ----
        c2a(H, A);
        binit(C, sUB1, t);
        mm_tile(A, sU1, C, lane);
        gather_h(bA + 16, bB + 16, A, t);   // s1 words 16..31 (L1 hit)
        mm_tile(A, sU1 + 8 * 32, C, lane);
        lrelu16(C);

        c2a(C, A);
        binit(H, sUB2, t);
        mm_tile(A, sU2, H, lane);       // H = h2

        // ---- head ----
        c2a(H, A);
        pqinit(C, sPH, sQH, aA, aB, t);
        mm_tile(A, sH1b, C, lane);
        lrelu16(C);
        c2a(C, A);
        binit(C, sHB2, t);
        mm_tile(A, sH2, C, lane);
        lrelu16(C);

        // head dot + row reduce
        float dA = 0.f, dB = 0.f;
#pragma unroll
        for (int nb = 0; nb < 4; nb++) {
            float2 h3 = *(const float2*)&sH3[8 * nb + 2 * t];
            dA = fmaf(C[nb][0], h3.x, dA); dA = fmaf(C[nb][1], h3.y, dA);
            dB = fmaf(C[nb][2], h3.x, dB); dB = fmaf(C[nb][3], h3.y, dB);
        }
        dA += __shfl_xor_sync(0xffffffffu, dA, 1);
        dA += __shfl_xor_sync(0xffffffffu, dA, 2);
        dB += __shfl_xor_sync(0xffffffffu, dB, 1);
        dB += __shfl_xor_sync(0xffffffffu, dB, 2);

        if (t == 0) {
            float exA = __expf(dA + sHB3), exB = __expf(dB + sHB3);
            out[eA] = exA;
            out[eB] = exB;
            red_add1(&g_dsum[nA], exA);
            red_add1(&g_dsum[nB], exB);
        }
    }
}

// ---------------- K4: normalize ----------------
__global__ void k4(const int* __restrict__ idx, float* __restrict__ out) {
    int e = blockIdx.x * blockDim.x + threadIdx.x;
    if (e >= E_EDGES) return;
    out[e] = out[e] / g_dsum[idx[e]];
}

// ---------------- launcher ----------------
extern "C" void kernel_launch(void* const* d_in, const int* in_sizes, int n_in,
                              void* d_out, int out_size) {
    const float* ea   = (const float*)d_in[0];
    const int*   eidx = (const int*)d_in[1];
    const float* w_in = (const float*)d_in[2];
    const float* b_in = (const float*)d_in[3];
    const float* tw1  = (const float*)d_in[4];
    const float* tb1  = (const float*)d_in[5];
    const float* tw2  = (const float*)d_in[6];
    const float* tb2  = (const float*)d_in[7];
    const float* uw1  = (const float*)d_in[8];
    const float* ub1  = (const float*)d_in[9];
    const float* uw2  = (const float*)d_in[10];
    const float* ub2  = (const float*)d_in[11];
    const float* hw1  = (const float*)d_in[12];
    const float* hb1  = (const float*)d_in[13];
    const float* hw2  = (const float*)d_in[14];
    const float* hb2  = (const float*)d_in[15];
    const float* hw3  = (const float*)d_in[16];
    const float* hb3  = (const float*)d_in[17];
    float* out = (float*)d_out;

    const int TB = 256;
    kinit<<<(N_NODES * D + TB - 1) / TB, TB>>>();
    const int GB = 4096;   // 128-thread blocks, 4 warp-tiles each
    int gcv = (N_NODES * 16 + TB - 1) / TB;
    k0<<<GB, 128>>>(ea, eidx, w_in, b_in, tw1, tb1, tw2, tb2);
    kcvt0<<<gcv, TB>>>();
    k1<<<GB, 128>>>(ea, eidx, w_in, b_in, tw1, tb1, tw2, tb2, uw1, ub1, uw2, ub2);
    kcvt1<<<gcv, TB>>>();
    k2<<<GB, 128>>>(ea, eidx, w_in, b_in, uw1, ub1, uw2, ub2,
                    hw1, hb1, hw2, hb2, hw3, hb3, out);
    int gb = (E_EDGES + TB - 1) / TB;
    k4<<<gb, TB>>>(eidx, out);
}

// round 9
// speedup vs baseline: 1.4575x; 1.1016x over previous
#include <cuda_runtime.h>

#define E_EDGES 2000000
#define N_NODES 50000
#define D 32
#define NTILES (E_EDGES / 16)

// ---------------- scratch ----------------
__device__ float    g_s0[N_NODES * D];          // segment sums layer 0 (fp32 accum)
__device__ float    g_s1[N_NODES * D];          // segment sums layer 1 (fp32 accum)
__device__ unsigned g_sh[N_NODES * 32];         // fp16 table (PERMUTED): [node][32]; 0-15 s0, 16-31 s1
__device__ uint2    g_h1h[(size_t)NTILES * 128];// h1 A-fragments (fp16), [tile][4][lane]
__device__ float    g_dsum[N_NODES];            // softmax denominators

__device__ __forceinline__ float lrelu(float x) { return fmaxf(x, 0.01f * x); }
__device__ __forceinline__ void red_add2(float* p, float a, float b) {
    asm volatile("red.global.add.v2.f32 [%0], {%1,%2};" :: "l"(p), "f"(a), "f"(b) : "memory");
}
__device__ __forceinline__ void red_add1(float* p, float v) {
    asm volatile("red.global.add.f32 [%0], %1;" :: "l"(p), "f"(v) : "memory");
}
__device__ __forceinline__ unsigned packh2(float lo, float hi) {
    unsigned r; asm("cvt.rn.f16x2.f32 %0, %1, %2;" : "=r"(r) : "f"(hi), "f"(lo)); return r;
}

__device__ __forceinline__ void mma16(float& c0, float& c1, float& c2, float& c3,
                                      unsigned a0, unsigned a1, unsigned a2, unsigned a3,
                                      unsigned b0, unsigned b1) {
    asm("mma.sync.aligned.m16n8k16.row.col.f32.f16.f16.f32 "
        "{%0,%1,%2,%3},{%4,%5,%6,%7},{%8,%9},{%0,%1,%2,%3};"
        : "+f"(c0), "+f"(c1), "+f"(c2), "+f"(c3)
        : "r"(a0), "r"(a1), "r"(a2), "r"(a3), "r"(b0), "r"(b1));
}

// MMA tile from REGISTER-resident weights
__device__ __forceinline__ void mm_tile_r(const unsigned A[2][4], const uint2 W[8],
                                          float C[4][4]) {
#pragma unroll
    for (int kb = 0; kb < 2; kb++)
#pragma unroll
        for (int nb = 0; nb < 4; nb++) {
            uint2 b = W[kb * 4 + nb];
            mma16(C[nb][0], C[nb][1], C[nb][2], C[nb][3],
                  A[kb][0], A[kb][1], A[kb][2], A[kb][3], b.x, b.y);
        }
}
// MMA tile from SMEM weights (for the kernels' overflow matmuls)
__device__ __forceinline__ void mm_tile_s(const unsigned A[2][4], const uint2* sB,
                                          float C[4][4], int lane) {
#pragma unroll
    for (int kb = 0; kb < 2; kb++)
#pragma unroll
        for (int nb = 0; nb < 4; nb++) {
            uint2 b = sB[(kb * 4 + nb) * 32 + lane];
            mma16(C[nb][0], C[nb][1], C[nb][2], C[nb][3],
                  A[kb][0], A[kb][1], A[kb][2], A[kb][3], b.x, b.y);
        }
}

__device__ __forceinline__ void c2a(const float C[4][4], unsigned A[2][4]) {
#pragma unroll
    for (int kb = 0; kb < 2; kb++) {
        A[kb][0] = packh2(C[2 * kb][0],     C[2 * kb][1]);
        A[kb][1] = packh2(C[2 * kb][2],     C[2 * kb][3]);
        A[kb][2] = packh2(C[2 * kb + 1][0], C[2 * kb + 1][1]);
        A[kb][3] = packh2(C[2 * kb + 1][2], C[2 * kb + 1][3]);
    }
}
__device__ __forceinline__ void lrelu16(float C[4][4]) {
#pragma unroll
    for (int b = 0; b < 4; b++)
#pragma unroll
        for (int r = 0; r < 4; r++) C[b][r] = lrelu(C[b][r]);
}

// PERMUTED fp16 gather: 2 LDG.64 per node row (words for this lane adjacent)
__device__ __forceinline__ void gather_p(const uint2* __restrict__ r0,
                                         const uint2* __restrict__ r1,
                                         unsigned A[2][4], int t) {
#pragma unroll
    for (int kb = 0; kb < 2; kb++) {
        uint2 v0 = r0[kb * 4 + t];
        uint2 v1 = r1[kb * 4 + t];
        A[kb][0] = v0.x; A[kb][2] = v0.y;
        A[kb][1] = v1.x; A[kb][3] = v1.y;
    }
}

// register bias init
__device__ __forceinline__ void binit_r(float C[4][4], const float b[8]) {
#pragma unroll
    for (int nb = 0; nb < 4; nb++) {
        C[nb][0] = b[2 * nb]; C[nb][1] = b[2 * nb + 1];
        C[nb][2] = b[2 * nb]; C[nb][3] = b[2 * nb + 1];
    }
}
// smem bias init
__device__ __forceinline__ void binit_s(float C[4][4], const float* sB, int t) {
#pragma unroll
    for (int nb = 0; nb < 4; nb++) {
        float2 B2 = *(const float2*)&sB[8 * nb + 2 * t];
        C[nb][0] = B2.x; C[nb][1] = B2.y; C[nb][2] = B2.x; C[nb][3] = B2.y;
    }
}
// register rank-1-fold init
__device__ __forceinline__ void pqinit_r(float C[4][4], const float P[8], const float Q[8],
                                         float aA, float aB) {
#pragma unroll
    for (int nb = 0; nb < 4; nb++) {
        C[nb][0] = fmaf(aA, P[2 * nb], Q[2 * nb]);
        C[nb][1] = fmaf(aA, P[2 * nb + 1], Q[2 * nb + 1]);
        C[nb][2] = fmaf(aB, P[2 * nb], Q[2 * nb]);
        C[nb][3] = fmaf(aB, P[2 * nb + 1], Q[2 * nb + 1]);
    }
}
__device__ __forceinline__ void ldvec8(float d[8], const float* s, int t) {
#pragma unroll
    for (int nb = 0; nb < 4; nb++) {
        float2 v = *(const float2*)&s[8 * nb + 2 * t];
        d[2 * nb] = v.x; d[2 * nb + 1] = v.y;
    }
}
__device__ __forceinline__ void ldw8(uint2 W[8], const uint2* s, int lane) {
#pragma unroll
    for (int p = 0; p < 8; p++) W[p] = s[p * 32 + lane];
}

__device__ __forceinline__ void scat(float* pA, float* pB, const float C[4][4], int t) {
#pragma unroll
    for (int nb = 0; nb < 4; nb++) {
        int u0 = 8 * nb + 2 * t;
        red_add2(pA + u0, C[nb][0], C[nb][1]);
        red_add2(pB + u0, C[nb][2], C[nb][3]);
    }
}

__device__ void fill_bfrag(uint2* dst, const float* __restrict__ W, int kblocks) {
    for (int i = threadIdx.x; i < kblocks * 4 * 32; i += blockDim.x) {
        int lane = i & 31, pi = i >> 5;
        int kb = pi >> 2, nb = pi & 3;
        int t = lane & 3, g = lane >> 2;
        int col = 8 * nb + g;
        int k0r = 16 * kb + 2 * t;
        uint2 v;
        v.x = packh2(W[k0r * 32 + col],       W[(k0r + 1) * 32 + col]);
        v.y = packh2(W[(k0r + 8) * 32 + col], W[(k0r + 9) * 32 + col]);
        dst[pi * 32 + lane] = v;
    }
}

// ---------------- init / convert ----------------
__global__ void kinit() {
    int i = blockIdx.x * blockDim.x + threadIdx.x;
    if (i < N_NODES * D) { g_s0[i] = 0.f; g_s1[i] = 0.f; }
    if (i < N_NODES)     { g_dsum[i] = 0.f; }
}
// permuted slot: word c (cols 2c,2c+1) -> slot kb*8 + 2t + h
__device__ __forceinline__ int slot_(int c) {
    int kb = c >> 3, j = c & 7, t = j & 3, h = j >> 2;
    return kb * 8 + 2 * t + h;
}
__global__ void kcvt0() {
    int i = blockIdx.x * blockDim.x + threadIdx.x;
    if (i >= N_NODES * 16) return;
    int n = i >> 4, c = i & 15;
    g_sh[n * 32 + slot_(c)] = packh2(g_s0[n * 32 + 2 * c], g_s0[n * 32 + 2 * c + 1]);
}
__global__ void kcvt1() {
    int i = blockIdx.x * blockDim.x + threadIdx.x;
    if (i >= N_NODES * 16) return;
    int n = i >> 4, c = i & 15;
    g_sh[n * 32 + 16 + slot_(c)] = packh2(g_s1[n * 32 + 2 * c], g_s1[n * 32 + 2 * c + 1]);
}

// ---------------- K0: t0 = TMLP0(h0) (rank-1 folded) -> scatter s0 ----------------
__global__ __launch_bounds__(128, 5)
void k0(const float* __restrict__ ea, const int* __restrict__ idx,
        const float* __restrict__ w_in, const float* __restrict__ b_in,
        const float* __restrict__ tw1, const float* __restrict__ tb1,
        const float* __restrict__ tw2, const float* __restrict__ tb2) {
    __shared__ uint2 sT2[256];
    __shared__ __align__(8) float sPT[32], sQT[32], sTB2[32];
    int tid = threadIdx.x;
    if (tid < 32) {
        float p = 0.f, qv = 0.f;
        for (int k = 0; k < 32; ++k) {
            p  = fmaf(w_in[k], tw1[k * 32 + tid], p);
            qv = fmaf(b_in[k], tw1[k * 32 + tid], qv);
        }
        sPT[tid] = p; sQT[tid] = qv + tb1[tid];
        sTB2[tid] = tb2[tid];
    }
    fill_bfrag(sT2, tw2, 2);
    __syncthreads();

    int lane = tid & 31, warp = tid >> 5;
    int t = lane & 3, g = lane >> 2;
    // register-resident weights / consts
    uint2 Wt2[8]; ldw8(Wt2, sT2, lane);
    float Bt2[8]; ldvec8(Bt2, sTB2, t);
    float Pr[8], Qr[8];
#pragma unroll
    for (int kb = 0; kb < 2; kb++) {
        int c0 = 16 * kb + 2 * t;
        float2 a = *(const float2*)&sPT[c0], b = *(const float2*)&sPT[c0 + 8];
        Pr[4 * kb] = a.x; Pr[4 * kb + 1] = a.y; Pr[4 * kb + 2] = b.x; Pr[4 * kb + 3] = b.y;
        float2 c = *(const float2*)&sQT[c0], d = *(const float2*)&sQT[c0 + 8];
        Qr[4 * kb] = c.x; Qr[4 * kb + 1] = c.y; Qr[4 * kb + 2] = d.x; Qr[4 * kb + 3] = d.y;
    }

    for (int tile = blockIdx.x * 4 + warp; tile < NTILES; tile += gridDim.x * 4) {
        int e0 = tile * 16;
        int eA = e0 + g, eB = eA + 8;
        float aA = ea[eA], aB = ea[eB];
        int nA = idx[eA], nB = idx[eB];

        unsigned A[2][4];
#pragma unroll
        for (int kb = 0; kb < 2; kb++) {
            A[kb][0] = packh2(lrelu(fmaf(aA, Pr[4 * kb], Qr[4 * kb])),
                              lrelu(fmaf(aA, Pr[4 * kb + 1], Qr[4 * kb + 1])));
            A[kb][1] = packh2(lrelu(fmaf(aB, Pr[4 * kb], Qr[4 * kb])),
                              lrelu(fmaf(aB, Pr[4 * kb + 1], Qr[4 * kb + 1])));
            A[kb][2] = packh2(lrelu(fmaf(aA, Pr[4 * kb + 2], Qr[4 * kb + 2])),
                              lrelu(fmaf(aA, Pr[4 * kb + 3], Qr[4 * kb + 3])));
            A[kb][3] = packh2(lrelu(fmaf(aB, Pr[4 * kb + 2], Qr[4 * kb + 2])),
                              lrelu(fmaf(aB, Pr[4 * kb + 3], Qr[4 * kb + 3])));
        }
        float C[4][4];
        binit_r(C, Bt2);
        mm_tile_r(A, Wt2, C);
        scat(g_s0 + (size_t)nA * 32, g_s0 + (size_t)nB * 32, C, t);
    }
}

// ---------------- K1: h1 = UPD0(h0,s0h); store h1 frags; t1 = TMLP1 -> scatter s1 --
__global__ __launch_bounds__(128, 3)
void k1(const float* __restrict__ ea, const int* __restrict__ idx,
        const float* __restrict__ w_in, const float* __restrict__ b_in,
        const float* __restrict__ tw1, const float* __restrict__ tb1,
        const float* __restrict__ tw2, const float* __restrict__ tb2,
        const float* __restrict__ uw1, const float* __restrict__ ub1,
        const float* __restrict__ uw2, const float* __restrict__ ub2) {
    __shared__ uint2 sU1b[256], sU2[256], sT1[256], sT2[256];
    __shared__ __align__(8) float sPU[32], sQU[32], sUB2[32], sTB1[32], sTB2[32];
    int tid = threadIdx.x;
    if (tid < 32) {
        float p = 0.f, qv = 0.f;
        for (int k = 0; k < 32; ++k) {
            p  = fmaf(w_in[k], uw1[k * 32 + tid], p);
            qv = fmaf(b_in[k], uw1[k * 32 + tid], qv);
        }
        sPU[tid] = p; sQU[tid] = qv + ub1[tid];
        sUB2[tid] = ub2[tid];
        sTB1[tid] = tb1[32 + tid];
        sTB2[tid] = tb2[32 + tid];
    }
    fill_bfrag(sU1b, uw1 + 1024, 2);
    fill_bfrag(sU2,  uw2, 2);
    fill_bfrag(sT1,  tw1 + 1024, 2);
    fill_bfrag(sT2,  tw2 + 1024, 2);
    __syncthreads();

    int lane = tid & 31, warp = tid >> 5;
    int t = lane & 3, g = lane >> 2;
    uint2 Wu1b[8], Wu2[8], Wt1[8];
    ldw8(Wu1b, sU1b, lane); ldw8(Wu2, sU2, lane); ldw8(Wt1, sT1, lane);
    float Pr[8], Qr[8], Bu2[8], Bt1[8];
    ldvec8(Pr, sPU, t); ldvec8(Qr, sQU, t);
    ldvec8(Bu2, sUB2, t); ldvec8(Bt1, sTB1, t);

    for (int tile = blockIdx.x * 4 + warp; tile < NTILES; tile += gridDim.x * 4) {
        int e0 = tile * 16;
        int eA = e0 + g, eB = eA + 8;
        float aA = ea[eA], aB = ea[eB];
        int nA = idx[eA], nB = idx[eB];

        unsigned A[2][4];
        gather_p((const uint2*)g_sh + (size_t)nA * 16,
                 (const uint2*)g_sh + (size_t)nB * 16, A, t);

        float C[4][4];
        pqinit_r(C, Pr, Qr, aA, aB);
        mm_tile_r(A, Wu1b, C);
        lrelu16(C);
        c2a(C, A);

        float H[4][4];
        binit_r(H, Bu2);
        mm_tile_r(A, Wu2, H);           // H = h1
        c2a(H, A);

        // store h1 A-fragments
        {
            uint2* ph = g_h1h + (size_t)tile * 128;
#pragma unroll
            for (int kb = 0; kb < 2; kb++) {
                ph[(2 * kb) * 32 + lane]     = make_uint2(A[kb][0], A[kb][2]);
                ph[(2 * kb + 1) * 32 + lane] = make_uint2(A[kb][1], A[kb][3]);
            }
        }

        // T layer 1
        binit_r(C, Bt1);
        mm_tile_r(A, Wt1, C);
        lrelu16(C);
        c2a(C, A);
        binit_s(C, sTB2, t);
        mm_tile_s(A, sT2, C, lane);

        scat(g_s1 + (size_t)nA * 32, g_s1 + (size_t)nB * 32, C, t);
    }
}

// ---- K2: load h1 frags; h2 = UPD1(h1,s1h); head; exp; red denom -------------------
__global__ __launch_bounds__(128, 3)
void k2(const float* __restrict__ ea, const int* __restrict__ idx,
        const float* __restrict__ w_in, const float* __restrict__ b_in,
        const float* __restrict__ uw1, const float* __restrict__ ub1,
        const float* __restrict__ uw2, const float* __restrict__ ub2,
        const float* __restrict__ hw1, const float* __restrict__ hb1,
        const float* __restrict__ hw2, const float* __restrict__ hb2,
        const float* __restrict__ hw3, const float* __restrict__ hb3,
        float* __restrict__ out) {
    __shared__ uint2 sU1[512];                  // uw1[1] 64x32: kb0..1 h-part, kb2..3 s-part
    __shared__ uint2 sU2[256], sH1b[256], sH2[256];
    __shared__ __align__(8) float sUB1[32], sUB2[32], sPH[32], sQH[32], sHB2[32], sH3[32];
    __shared__ float sHB3;
    int tid = threadIdx.x;
    const float* u1 = uw1 + 2048;
    if (tid < 32) {
        float p = 0.f, qv = 0.f;
        for (int k = 0; k < 32; ++k) {
            p  = fmaf(w_in[k], hw1[k * 32 + tid], p);
            qv = fmaf(b_in[k], hw1[k * 32 + tid], qv);
        }
        sPH[tid] = p;  sQH[tid] = qv + hb1[tid];
        sUB1[tid] = ub1[32 + tid];
        sUB2[tid] = ub2[32 + tid];
        sHB2[tid] = hb2[tid];
        sH3[tid]  = hw3[tid];
    }
    if (tid == 0) sHB3 = hb3[0];
    fill_bfrag(sU1,  u1, 4);
    fill_bfrag(sU2,  uw2 + 1024, 2);
    fill_bfrag(sH1b, hw1 + 1024, 2);
    fill_bfrag(sH2,  hw2, 2);
    __syncthreads();

    int lane = tid & 31, warp = tid >> 5;
    int t = lane & 3, g = lane >> 2;
    uint2 Wu1h[8], Wu1s[8], Wu2[8];
    ldw8(Wu1h, sU1, lane); ldw8(Wu1s, sU1 + 8 * 32, lane); ldw8(Wu2, sU2, lane);
    float Bu1[8], Bu2[8], PHr[8], QHr[8], H3r[8];
    ldvec8(Bu1, sUB1, t); ldvec8(Bu2, sUB2, t);
    ldvec8(PHr, sPH, t);  ldvec8(QHr, sQH, t);
    ldvec8(H3r, sH3, t);
    float hb3v = sHB3;

    for (int tile = blockIdx.x * 4 + warp; tile < NTILES; tile += gridDim.x * 4) {
        int e0 = tile * 16;
        int eA = e0 + g, eB = eA + 8;
        float aA = ea[eA], aB = ea[eB];
        int nA = idx[eA], nB = idx[eB];

        // load h1 A-fragments (coalesced)
        unsigned A[2][4];
        {
            const uint2* ph = g_h1h + (size_t)tile * 128;
#pragma unroll
            for (int kb = 0; kb < 2; kb++) {
                uint2 v0 = ph[(2 * kb) * 32 + lane];
                uint2 v1 = ph[(2 * kb + 1) * 32 + lane];
                A[kb][0] = v0.x; A[kb][2] = v0.y;
                A[kb][1] = v1.x; A[kb][3] = v1.y;
            }
        }
        float C[4][4];
        binit_r(C, Bu1);
        mm_tile_r(A, Wu1h, C);
        gather_p((const uint2*)g_sh + (size_t)nA * 16 + 8,
                 (const uint2*)g_sh + (size_t)nB * 16 + 8, A, t);
        mm_tile_r(A, Wu1s, C);
        lrelu16(C);
        c2a(C, A);

        float H[4][4];
        binit_r(H, Bu2);
        mm_tile_r(A, Wu2, H);           // H = h2
        c2a(H, A);

        // head
        pqinit_r(C, PHr, QHr, aA, aB);
        mm_tile_s(A, sH1b, C, lane);
        lrelu16(C);
        c2a(C, A);
        binit_s(C, sHB2, t);
        mm_tile_s(A, sH2, C, lane);
        lrelu16(C);

        float dA = 0.f, dB = 0.f;
#pragma unroll
        for (int nb = 0; nb < 4; nb++) {
            dA = fmaf(C[nb][0], H3r[2 * nb], dA); dA = fmaf(C[nb][1], H3r[2 * nb + 1], dA);
            dB = fmaf(C[nb][2], H3r[2 * nb], dB); dB = fmaf(C[nb][3], H3r[2 * nb + 1], dB);
        }
        dA += __shfl_xor_sync(0xffffffffu, dA, 1);
        dA += __shfl_xor_sync(0xffffffffu, dA, 2);
        dB += __shfl_xor_sync(0xffffffffu, dB, 1);
        dB += __shfl_xor_sync(0xffffffffu, dB, 2);

        if (t == 0) {
            float exA = __expf(dA + hb3v), exB = __expf(dB + hb3v);
            out[eA] = exA;
            out[eB] = exB;
            red_add1(&g_dsum[nA], exA);
            red_add1(&g_dsum[nB], exB);
        }
    }
}

// ---------------- K4: normalize ----------------
__global__ void k4(const int* __restrict__ idx, float* __restrict__ out) {
    int e = blockIdx.x * blockDim.x + threadIdx.x;
    if (e >= E_EDGES) return;
    out[e] = out[e] / g_dsum[idx[e]];
}

// ---------------- launcher ----------------
extern "C" void kernel_launch(void* const* d_in, const int* in_sizes, int n_in,
                              void* d_out, int out_size) {
    const float* ea   = (const float*)d_in[0];
    const int*   eidx = (const int*)d_in[1];
    const float* w_in = (const float*)d_in[2];
    const float* b_in = (const float*)d_in[3];
    const float* tw1  = (const float*)d_in[4];
    const float* tb1  = (const float*)d_in[5];
    const float* tw2  = (const float*)d_in[6];
    const float* tb2  = (const float*)d_in[7];
    const float* uw1  = (const float*)d_in[8];
    const float* ub1  = (const float*)d_in[9];
    const float* uw2  = (const float*)d_in[10];
    const float* ub2  = (const float*)d_in[11];
    const float* hw1  = (const float*)d_in[12];
    const float* hb1  = (const float*)d_in[13];
    const float* hw2  = (const float*)d_in[14];
    const float* hb2  = (const float*)d_in[15];
    const float* hw3  = (const float*)d_in[16];
    const float* hb3  = (const float*)d_in[17];
    float* out = (float*)d_out;

    const int TB = 256;
    kinit<<<(N_NODES * D + TB - 1) / TB, TB>>>();
    const int GB = 2048;   // 128-thread blocks, 4 warp-tiles each, grid-stride
    int gcv = (N_NODES * 16 + TB - 1) / TB;
    k0<<<GB, 128>>>(ea, eidx, w_in, b_in, tw1, tb1, tw2, tb2);
    kcvt0<<<gcv, TB>>>();
    k1<<<GB, 128>>>(ea, eidx, w_in, b_in, tw1, tb1, tw2, tb2, uw1, ub1, uw2, ub2);
    kcvt1<<<gcv, TB>>>();
    k2<<<GB, 128>>>(ea, eidx, w_in, b_in, uw1, ub1, uw2, ub2,
                    hw1, hb1, hw2, hb2, hw3, hb3, out);
    int gb = (E_EDGES + TB - 1) / TB;
    k4<<<gb, TB>>>(eidx, out);
}

// round 10
// speedup vs baseline: 1.6226x; 1.1133x over previous
#include <cuda_runtime.h>

#define E_EDGES 2000000
#define N_NODES 50000
#define D 32
#define NTILES (E_EDGES / 16)

// ---------------- scratch ----------------
__device__ float    g_s0[N_NODES * D];          // segment sums layer 0 (fp32 accum)
__device__ float    g_s1[N_NODES * D];          // segment sums layer 1 (fp32 accum)
__device__ unsigned g_sh[N_NODES * 32];         // fp16 table (PERMUTED): [node][32]; 0-15 s0, 16-31 s1
__device__ uint2    g_h1h[(size_t)NTILES * 128];// h1 A-fragments (fp16), [tile][4][lane]
__device__ float    g_dsum[N_NODES];            // softmax denominators

__device__ __forceinline__ float lrelu(float x) { return fmaxf(x, 0.01f * x); }
__device__ __forceinline__ void red_add2(float* p, float a, float b) {
    asm volatile("red.global.add.v2.f32 [%0], {%1,%2};" :: "l"(p), "f"(a), "f"(b) : "memory");
}
__device__ __forceinline__ void red_add1(float* p, float v) {
    asm volatile("red.global.add.f32 [%0], %1;" :: "l"(p), "f"(v) : "memory");
}
__device__ __forceinline__ unsigned packh2(float lo, float hi) {
    unsigned r; asm("cvt.rn.f16x2.f32 %0, %1, %2;" : "=r"(r) : "f"(hi), "f"(lo)); return r;
}

__device__ __forceinline__ void mma16(float& c0, float& c1, float& c2, float& c3,
                                      unsigned a0, unsigned a1, unsigned a2, unsigned a3,
                                      unsigned b0, unsigned b1) {
    asm("mma.sync.aligned.m16n8k16.row.col.f32.f16.f16.f32 "
        "{%0,%1,%2,%3},{%4,%5,%6,%7},{%8,%9},{%0,%1,%2,%3};"
        : "+f"(c0), "+f"(c1), "+f"(c2), "+f"(c3)
        : "r"(a0), "r"(a1), "r"(a2), "r"(a3), "r"(b0), "r"(b1));
}

__device__ __forceinline__ void mm_tile_r(const unsigned A[2][4], const uint2 W[8],
                                          float C[4][4]) {
#pragma unroll
    for (int kb = 0; kb < 2; kb++)
#pragma unroll
        for (int nb = 0; nb < 4; nb++) {
            uint2 b = W[kb * 4 + nb];
            mma16(C[nb][0], C[nb][1], C[nb][2], C[nb][3],
                  A[kb][0], A[kb][1], A[kb][2], A[kb][3], b.x, b.y);
        }
}
__device__ __forceinline__ void mm_tile_s(const unsigned A[2][4], const uint2* sB,
                                          float C[4][4], int lane) {
#pragma unroll
    for (int kb = 0; kb < 2; kb++)
#pragma unroll
        for (int nb = 0; nb < 4; nb++) {
            uint2 b = sB[(kb * 4 + nb) * 32 + lane];
            mma16(C[nb][0], C[nb][1], C[nb][2], C[nb][3],
                  A[kb][0], A[kb][1], A[kb][2], A[kb][3], b.x, b.y);
        }
}

__device__ __forceinline__ void c2a(const float C[4][4], unsigned A[2][4]) {
#pragma unroll
    for (int kb = 0; kb < 2; kb++) {
        A[kb][0] = packh2(C[2 * kb][0],     C[2 * kb][1]);
        A[kb][1] = packh2(C[2 * kb][2],     C[2 * kb][3]);
        A[kb][2] = packh2(C[2 * kb + 1][0], C[2 * kb + 1][1]);
        A[kb][3] = packh2(C[2 * kb + 1][2], C[2 * kb + 1][3]);
    }
}
__device__ __forceinline__ void lrelu16(float C[4][4]) {
#pragma unroll
    for (int b = 0; b < 4; b++)
#pragma unroll
        for (int r = 0; r < 4; r++) C[b][r] = lrelu(C[b][r]);
}

// PERMUTED fp16 gather: 2 LDG.64 per node row
__device__ __forceinline__ void gather_p(const uint2* __restrict__ r0,
                                         const uint2* __restrict__ r1,
                                         unsigned A[2][4], int t) {
#pragma unroll
    for (int kb = 0; kb < 2; kb++) {
        uint2 v0 = r0[kb * 4 + t];
        uint2 v1 = r1[kb * 4 + t];
        A[kb][0] = v0.x; A[kb][2] = v0.y;
        A[kb][1] = v1.x; A[kb][3] = v1.y;
    }
}

__device__ __forceinline__ void binit_s(float C[4][4], const float* sB, int t) {
#pragma unroll
    for (int nb = 0; nb < 4; nb++) {
        float2 B2 = *(const float2*)&sB[8 * nb + 2 * t];
        C[nb][0] = B2.x; C[nb][1] = B2.y; C[nb][2] = B2.x; C[nb][3] = B2.y;
    }
}
__device__ __forceinline__ void pqinit_s(float C[4][4], const float* sP, const float* sQ,
                                         float aA, float aB, int t) {
#pragma unroll
    for (int nb = 0; nb < 4; nb++) {
        float2 P = *(const float2*)&sP[8 * nb + 2 * t];
        float2 Q = *(const float2*)&sQ[8 * nb + 2 * t];
        C[nb][0] = fmaf(aA, P.x, Q.x); C[nb][1] = fmaf(aA, P.y, Q.y);
        C[nb][2] = fmaf(aB, P.x, Q.x); C[nb][3] = fmaf(aB, P.y, Q.y);
    }
}
__device__ __forceinline__ void ldw8(uint2 W[8], const uint2* s, int lane) {
#pragma unroll
    for (int p = 0; p < 8; p++) W[p] = s[p * 32 + lane];
}
__device__ __forceinline__ void cpA(unsigned D_[2][4], const unsigned S[2][4]) {
#pragma unroll
    for (int kb = 0; kb < 2; kb++)
#pragma unroll
        for (int r = 0; r < 4; r++) D_[kb][r] = S[kb][r];
}

__device__ __forceinline__ void scat(float* pA, float* pB, const float C[4][4], int t) {
#pragma unroll
    for (int nb = 0; nb < 4; nb++) {
        int u0 = 8 * nb + 2 * t;
        red_add2(pA + u0, C[nb][0], C[nb][1]);
        red_add2(pB + u0, C[nb][2], C[nb][3]);
    }
}

__device__ void fill_bfrag(uint2* dst, const float* __restrict__ W, int kblocks) {
    for (int i = threadIdx.x; i < kblocks * 4 * 32; i += blockDim.x) {
        int lane = i & 31, pi = i >> 5;
        int kb = pi >> 2, nb = pi & 3;
        int t = lane & 3, g = lane >> 2;
        int col = 8 * nb + g;
        int k0r = 16 * kb + 2 * t;
        uint2 v;
        v.x = packh2(W[k0r * 32 + col],       W[(k0r + 1) * 32 + col]);
        v.y = packh2(W[(k0r + 8) * 32 + col], W[(k0r + 9) * 32 + col]);
        dst[pi * 32 + lane] = v;
    }
}

// ---------------- init / convert ----------------
__global__ void kinit() {
    int i = blockIdx.x * blockDim.x + threadIdx.x;
    if (i < N_NODES * D) { g_s0[i] = 0.f; g_s1[i] = 0.f; }
    if (i < N_NODES)     { g_dsum[i] = 0.f; }
}
__device__ __forceinline__ int slot_(int c) {
    int kb = c >> 3, j = c & 7, t = j & 3, h = j >> 2;
    return kb * 8 + 2 * t + h;
}
__global__ void kcvt0() {
    int i = blockIdx.x * blockDim.x + threadIdx.x;
    if (i >= N_NODES * 16) return;
    int n = i >> 4, c = i & 15;
    g_sh[n * 32 + slot_(c)] = packh2(g_s0[n * 32 + 2 * c], g_s0[n * 32 + 2 * c + 1]);
}
__global__ void kcvt1() {
    int i = blockIdx.x * blockDim.x + threadIdx.x;
    if (i >= N_NODES * 16) return;
    int n = i >> 4, c = i & 15;
    g_sh[n * 32 + 16 + slot_(c)] = packh2(g_s1[n * 32 + 2 * c], g_s1[n * 32 + 2 * c + 1]);
}

// ---------------- K0: t0 = TMLP0(h0) (rank-1 folded) -> scatter s0 ----------------
__global__ __launch_bounds__(128, 5)
void k0(const float* __restrict__ ea, const int* __restrict__ idx,
        const float* __restrict__ w_in, const float* __restrict__ b_in,
        const float* __restrict__ tw1, const float* __restrict__ tb1,
        const float* __restrict__ tw2, const float* __restrict__ tb2) {
    __shared__ uint2 sT2[256];
    __shared__ __align__(8) float sPT[32], sQT[32], sTB2[32];
    int tid = threadIdx.x;
    if (tid < 32) {
        float p = 0.f, qv = 0.f;
        for (int k = 0; k < 32; ++k) {
            p  = fmaf(w_in[k], tw1[k * 32 + tid], p);
            qv = fmaf(b_in[k], tw1[k * 32 + tid], qv);
        }
        sPT[tid] = p; sQT[tid] = qv + tb1[tid];
        sTB2[tid] = tb2[tid];
    }
    fill_bfrag(sT2, tw2, 2);
    __syncthreads();

    int lane = tid & 31, warp = tid >> 5;
    int t = lane & 3, g = lane >> 2;
    uint2 Wt2[8]; ldw8(Wt2, sT2, lane);

    for (int tile = blockIdx.x * 4 + warp; tile < NTILES; tile += gridDim.x * 4) {
        int e0 = tile * 16;
        int eA = e0 + g, eB = eA + 8;
        float aA = ea[eA], aB = ea[eB];
        int nA = idx[eA], nB = idx[eB];

        unsigned A[2][4];
#pragma unroll
        for (int kb = 0; kb < 2; kb++) {
            int c0 = 16 * kb + 2 * t;
            float2 P0 = *(const float2*)&sPT[c0],     Q0 = *(const float2*)&sQT[c0];
            float2 P1 = *(const float2*)&sPT[c0 + 8], Q1 = *(const float2*)&sQT[c0 + 8];
            A[kb][0] = packh2(lrelu(fmaf(aA, P0.x, Q0.x)), lrelu(fmaf(aA, P0.y, Q0.y)));
            A[kb][1] = packh2(lrelu(fmaf(aB, P0.x, Q0.x)), lrelu(fmaf(aB, P0.y, Q0.y)));
            A[kb][2] = packh2(lrelu(fmaf(aA, P1.x, Q1.x)), lrelu(fmaf(aA, P1.y, Q1.y)));
            A[kb][3] = packh2(lrelu(fmaf(aB, P1.x, Q1.x)), lrelu(fmaf(aB, P1.y, Q1.y)));
        }
        float C[4][4];
        binit_s(C, sTB2, t);
        mm_tile_r(A, Wt2, C);
        scat(g_s0 + (size_t)nA * 32, g_s0 + (size_t)nB * 32, C, t);
    }
}

// ---------------- K1: pipelined; h1 = UPD0; store h1 frags; t1 = TMLP1 -> s1 -------
__global__ __launch_bounds__(128, 4)
void k1(const float* __restrict__ ea, const int* __restrict__ idx,
        const float* __restrict__ w_in, const float* __restrict__ b_in,
        const float* __restrict__ tw1, const float* __restrict__ tb1,
        const float* __restrict__ tw2, const float* __restrict__ tb2,
        const float* __restrict__ uw1, const float* __restrict__ ub1,
        const float* __restrict__ uw2, const float* __restrict__ ub2) {
    __shared__ uint2 sU1b[256], sU2[256], sT1[256], sT2[256];
    __shared__ __align__(8) float sPU[32], sQU[32], sUB2[32], sTB1[32], sTB2[32];
    int tid = threadIdx.x;
    if (tid < 32) {
        float p = 0.f, qv = 0.f;
        for (int k = 0; k < 32; ++k) {
            p  = fmaf(w_in[k], uw1[k * 32 + tid], p);
            qv = fmaf(b_in[k], uw1[k * 32 + tid], qv);
        }
        sPU[tid] = p; sQU[tid] = qv + ub1[tid];
        sUB2[tid] = ub2[tid];
        sTB1[tid] = tb1[32 + tid];
        sTB2[tid] = tb2[32 + tid];
    }
    fill_bfrag(sU1b, uw1 + 1024, 2);
    fill_bfrag(sU2,  uw2, 2);
    fill_bfrag(sT1,  tw1 + 1024, 2);
    fill_bfrag(sT2,  tw2 + 1024, 2);
    __syncthreads();

    int lane = tid & 31, warp = tid >> 5;
    int t = lane & 3, g = lane >> 2;
    uint2 Wu1b[8], Wu2[8];
    ldw8(Wu1b, sU1b, lane); ldw8(Wu2, sU2, lane);

    const int stride = gridDim.x * 4;
    int tile = blockIdx.x * 4 + warp;
    if (tile >= NTILES) return;

    // prologue: gather for first tile
    float aA = ea[tile * 16 + g], aB = ea[tile * 16 + g + 8];
    int nA = idx[tile * 16 + g], nB = idx[tile * 16 + g + 8];
    unsigned A[2][4];
    gather_p((const uint2*)g_sh + (size_t)nA * 16,
             (const uint2*)g_sh + (size_t)nB * 16, A, t);

    while (true) {
        int tn = tile + stride;
        bool has = tn < NTILES;
        int tc = has ? tn : tile;
        // prefetch next tile's inputs + gather
        float aAn = ea[tc * 16 + g], aBn = ea[tc * 16 + g + 8];
        int nAn = idx[tc * 16 + g], nBn = idx[tc * 16 + g + 8];
        unsigned An[2][4];
        gather_p((const uint2*)g_sh + (size_t)nAn * 16,
                 (const uint2*)g_sh + (size_t)nBn * 16, An, t);

        // ---- current tile chain ----
        float C[4][4];
        pqinit_s(C, sPU, sQU, aA, aB, t);
        mm_tile_r(A, Wu1b, C);
        lrelu16(C);
        c2a(C, A);

        float H[4][4];
        binit_s(H, sUB2, t);
        mm_tile_r(A, Wu2, H);           // H = h1
        c2a(H, A);

        // store h1 A-fragments
        {
            uint2* ph = g_h1h + (size_t)tile * 128;
#pragma unroll
            for (int kb = 0; kb < 2; kb++) {
                ph[(2 * kb) * 32 + lane]     = make_uint2(A[kb][0], A[kb][2]);
                ph[(2 * kb + 1) * 32 + lane] = make_uint2(A[kb][1], A[kb][3]);
            }
        }

        // T layer 1 (smem weights)
        binit_s(C, sTB1, t);
        mm_tile_s(A, sT1, C, lane);
        lrelu16(C);
        c2a(C, A);
        binit_s(C, sTB2, t);
        mm_tile_s(A, sT2, C, lane);

        scat(g_s1 + (size_t)nA * 32, g_s1 + (size_t)nB * 32, C, t);

        if (!has) break;
        tile = tn;
        aA = aAn; aB = aBn; nA = nAn; nB = nBn;
        cpA(A, An);
    }
}

// ---- K2: pipelined; h2 = UPD1(h1 frags, s1h); head; exp; red denom ----------------
__global__ __launch_bounds__(128, 4)
void k2(const float* __restrict__ ea, const int* __restrict__ idx,
        const float* __restrict__ w_in, const float* __restrict__ b_in,
        const float* __restrict__ uw1, const float* __restrict__ ub1,
        const float* __restrict__ uw2, const float* __restrict__ ub2,
        const float* __restrict__ hw1, const float* __restrict__ hb1,
        const float* __restrict__ hw2, const float* __restrict__ hb2,
        const float* __restrict__ hw3, const float* __restrict__ hb3,
        float* __restrict__ out) {
    __shared__ uint2 sU1[512];                  // uw1[1]: kb0..1 h-part, kb2..3 s-part
    __shared__ uint2 sU2[256], sH1b[256], sH2[256];
    __shared__ __align__(8) float sUB1[32], sUB2[32], sPH[32], sQH[32], sHB2[32], sH3[32];
    __shared__ float sHB3;
    int tid = threadIdx.x;
    const float* u1 = uw1 + 2048;
    if (tid < 32) {
        float p = 0.f, qv = 0.f;
        for (int k = 0; k < 32; ++k) {
            p  = fmaf(w_in[k], hw1[k * 32 + tid], p);
            qv = fmaf(b_in[k], hw1[k * 32 + tid], qv);
        }
        sPH[tid] = p;  sQH[tid] = qv + hb1[tid];
        sUB1[tid] = ub1[32 + tid];
        sUB2[tid] = ub2[32 + tid];
        sHB2[tid] = hb2[tid];
        sH3[tid]  = hw3[tid];
    }
    if (tid == 0) sHB3 = hb3[0];
    fill_bfrag(sU1,  u1, 4);
    fill_bfrag(sU2,  uw2 + 1024, 2);
    fill_bfrag(sH1b, hw1 + 1024, 2);
    fill_bfrag(sH2,  hw2, 2);
    __syncthreads();

    int lane = tid & 31, warp = tid >> 5;
    int t = lane & 3, g = lane >> 2;
    uint2 Wu1h[8], Wu1s[8];
    ldw8(Wu1h, sU1, lane); ldw8(Wu1s, sU1 + 8 * 32, lane);
    float hb3v = sHB3;

    const int stride = gridDim.x * 4;
    int tile = blockIdx.x * 4 + warp;
    if (tile >= NTILES) return;

    // prologue: loads for first tile
    float aA = ea[tile * 16 + g], aB = ea[tile * 16 + g + 8];
    int nA = idx[tile * 16 + g], nB = idx[tile * 16 + g + 8];
    unsigned Ah[2][4], As[2][4];
    {
        const uint2* ph = g_h1h + (size_t)tile * 128;
#pragma unroll
        for (int kb = 0; kb < 2; kb++) {
            uint2 v0 = ph[(2 * kb) * 32 + lane];
            uint2 v1 = ph[(2 * kb + 1) * 32 + lane];
            Ah[kb][0] = v0.x; Ah[kb][2] = v0.y;
            Ah[kb][1] = v1.x; Ah[kb][3] = v1.y;
        }
    }
    gather_p((const uint2*)g_sh + (size_t)nA * 16 + 8,
             (const uint2*)g_sh + (size_t)nB * 16 + 8, As, t);

    while (true) {
        int tn = tile + stride;
        bool has = tn < NTILES;
        int tc = has ? tn : tile;
        // prefetch next tile
        float aAn = ea[tc * 16 + g], aBn = ea[tc * 16 + g + 8];
        int nAn = idx[tc * 16 + g], nBn = idx[tc * 16 + g + 8];
        unsigned Ahn[2][4], Asn[2][4];
        {
            const uint2* ph = g_h1h + (size_t)tc * 128;
#pragma unroll
            for (int kb = 0; kb < 2; kb++) {
                uint2 v0 = ph[(2 * kb) * 32 + lane];
                uint2 v1 = ph[(2 * kb + 1) * 32 + lane];
                Ahn[kb][0] = v0.x; Ahn[kb][2] = v0.y;
                Ahn[kb][1] = v1.x; Ahn[kb][3] = v1.y;
            }
        }
        gather_p((const uint2*)g_sh + (size_t)nAn * 16 + 8,
                 (const uint2*)g_sh + (size_t)nBn * 16 + 8, Asn, t);

        // ---- current tile chain ----
        float C[4][4];
        binit_s(C, sUB1, t);
        mm_tile_r(Ah, Wu1h, C);
        mm_tile_r(As, Wu1s, C);
        lrelu16(C);
        unsigned A[2][4];
        c2a(C, A);

        float H[4][4];
        binit_s(H, sUB2, t);
        mm_tile_s(A, sU2, H, lane);     // H = h2
        c2a(H, A);

        // head
        pqinit_s(C, sPH, sQH, aA, aB, t);
        mm_tile_s(A, sH1b, C, lane);
        lrelu16(C);
        c2a(C, A);
        binit_s(C, sHB2, t);
        mm_tile_s(A, sH2, C, lane);
        lrelu16(C);

        float dA = 0.f, dB = 0.f;
#pragma unroll
        for (int nb = 0; nb < 4; nb++) {
            float2 h3 = *(const float2*)&sH3[8 * nb + 2 * t];
            dA = fmaf(C[nb][0], h3.x, dA); dA = fmaf(C[nb][1], h3.y, dA);
            dB = fmaf(C[nb][2], h3.x, dB); dB = fmaf(C[nb][3], h3.y, dB);
        }
        dA += __shfl_xor_sync(0xffffffffu, dA, 1);
        dA += __shfl_xor_sync(0xffffffffu, dA, 2);
        dB += __shfl_xor_sync(0xffffffffu, dB, 1);
        dB += __shfl_xor_sync(0xffffffffu, dB, 2);

        if (t == 0) {
            float exA = __expf(dA + hb3v), exB = __expf(dB + hb3v);
            out[tile * 16 + g] = exA;
            out[tile * 16 + g + 8] = exB;
            red_add1(&g_dsum[nA], exA);
            red_add1(&g_dsum[nB], exB);
        }

        if (!has) break;
        tile = tn;
        aA = aAn; aB = aBn; nA = nAn; nB = nBn;
        cpA(Ah, Ahn); cpA(As, Asn);
    }
}

// ---------------- K4: normalize ----------------
__global__ void k4(const int* __restrict__ idx, float* __restrict__ out) {
    int e = blockIdx.x * blockDim.x + threadIdx.x;
    if (e >= E_EDGES) return;
    out[e] = out[e] / g_dsum[idx[e]];
}

// ---------------- launcher ----------------
extern "C" void kernel_launch(void* const* d_in, const int* in_sizes, int n_in,
                              void* d_out, int out_size) {
    const float* ea   = (const float*)d_in[0];
    const int*   eidx = (const int*)d_in[1];
    const float* w_in = (const float*)d_in[2];
    const float* b_in = (const float*)d_in[3];
    const float* tw1  = (const float*)d_in[4];
    const float* tb1  = (const float*)d_in[5];
    const float* tw2  = (const float*)d_in[6];
    const float* tb2  = (const float*)d_in[7];
    const float* uw1  = (const float*)d_in[8];
    const float* ub1  = (const float*)d_in[9];
    const float* uw2  = (const float*)d_in[10];
    const float* ub2  = (const float*)d_in[11];
    const float* hw1  = (const float*)d_in[12];
    const float* hb1  = (const float*)d_in[13];
    const float* hw2  = (const float*)d_in[14];
    const float* hb2  = (const float*)d_in[15];
    const float* hw3  = (const float*)d_in[16];
    const float* hb3  = (const float*)d_in[17];
    float* out = (float*)d_out;

    const int TB = 256;
    kinit<<<(N_NODES * D + TB - 1) / TB, TB>>>();
    const int GB = 2048;
    int gcv = (N_NODES * 16 + TB - 1) / TB;
    k0<<<GB, 128>>>(ea, eidx, w_in, b_in, tw1, tb1, tw2, tb2);
    kcvt0<<<gcv, TB>>>();
    k1<<<GB, 128>>>(ea, eidx, w_in, b_in, tw1, tb1, tw2, tb2, uw1, ub1, uw2, ub2);
    kcvt1<<<gcv, TB>>>();
    k2<<<GB, 128>>>(ea, eidx, w_in, b_in, uw1, ub1, uw2, ub2,
                    hw1, hb1, hw2, hb2, hw3, hb3, out);
    int gb = (E_EDGES + TB - 1) / TB;
    k4<<<gb, TB>>>(eidx, out);
}